// round 17
// baseline (speedup 1.0000x reference)
#include <cuda_runtime.h>
#include <cuda_bf16.h>
#include <math.h>

#define NJ 30000
#define NS 12000
#define E_JS 300000
#define E_SJ 300000
#define E_SS 150000
#define E_SS_T (E_SS + NS)
#define E_ALL (E_JS + E_SS_T + E_SJ)
#define SBERT 384
#define HID 128
#define HHID 256

// ---------------- scratch (device globals; no allocation allowed) ----------------
__device__ float g_xj[NJ * HID];
__device__ float g_xs[NS * HID];
__device__ float g_xs2[NS * HID];
__device__ __nv_bfloat16 g_hw0[NJ * HHID];
__device__ __nv_bfloat16 g_hw1[NS * HHID];
__device__ __nv_bfloat16 g_hw2[NS * HHID];
__device__ float g_hw1f[NS * HHID];          // layer-2 sj features in fp32 (precision)
__device__ float g_mw[2 * 3 * 128 * 256];
__device__ float g_fvj[2 * 4 * 128];
__device__ float g_fvs[2 * 8 * 128];
__device__ float g_cvj[2 * 128];
__device__ float g_cvs[2 * 128];
// alpj[n*4 + {0,1}] = alps0 ; {2,3} = alpd1 ; alp_s[n*8 + {0,1}]=alps1 {2,3}=alps2 {4,5}=alpd0 {6,7}=alpd2
__device__ float g_alpj[NJ * 4];
__device__ float g_alp_s[NS * 8];
#define CNTCUR_N (4 * NS + 2 * NJ)
__device__ int g_cntcur[CNTCUR_N];
__device__ int g_off_js[NS], g_off_ss[NS], g_off_sj[NJ];
__device__ int g_csr_js[E_JS];
__device__ int g_csr_ss[E_SS_T];
__device__ int g_csr_sj[E_SJ];

// ---------------- helpers ----------------
__device__ __forceinline__ float warp_sum(float v) {
    #pragma unroll
    for (int o = 16; o; o >>= 1) v += __shfl_xor_sync(0xffffffffu, v, o);
    return v;
}
__device__ __forceinline__ unsigned long long pk2(float lo, float hi) {
    unsigned long long r;
    asm("mov.b64 %0, {%1, %2};" : "=l"(r) : "r"(__float_as_uint(lo)), "r"(__float_as_uint(hi)));
    return r;
}
__device__ __forceinline__ void upk2(unsigned long long v, float& lo, float& hi) {
    unsigned int a, b;
    asm("mov.b64 {%0, %1}, %2;" : "=r"(a), "=r"(b) : "l"(v));
    lo = __uint_as_float(a); hi = __uint_as_float(b);
}
__device__ __forceinline__ void fma2(unsigned long long& d, unsigned long long a, unsigned long long b) {
    asm("fma.rn.f32x2 %0, %1, %2, %0;" : "+l"(d) : "l"(a), "l"(b));
}
__device__ __forceinline__ float2 bf2f(unsigned int u) {
    __nv_bfloat162 b = *(__nv_bfloat162*)&u;
    return __bfloat1622float2(b);
}

// ---------------- batched GEMM, compact 1D grid (up to 10 jobs) ----------------
// Per-job: N (128 or 256), K, tstart (tile prefix). Tiles row-major: tx = local/ntY, ty = local%ntY.
// Options: A2 (relu(A+A2) on load), bias, g/be (LN+relu, N==128), qv/sc (fused score, N==128),
// Cb (bf16 out), fv/alp/n_alpha/alp_ld (fused alpha dots on ty==0 tiles).
struct GJob {
    const float* A; const float* A2; const float* B; const float* bias;
    const float* g; const float* be; const float* qv; const float* fv;
    float* C; __nv_bfloat16* Cb; float* sc; float* alp;
    int M; int lda; int ldC; int n_alpha; int alp_ld; int N; int K; int tstart;
};
struct GJobs { GJob j[10]; };

__global__ __launch_bounds__(256) void gemm_kernel(GJobs js)
{
    // locate job
    int b = blockIdx.x;
    int z = 0;
    #pragma unroll
    for (int i = 1; i < 10; i++)
        if (js.j[i].A != nullptr && js.j[i].tstart <= b) z = i;
    GJob jb = js.j[z];
    const int local = b - jb.tstart;
    const int ntY = jb.N >> 7;
    const int tx = local / ntY;
    const int ty = local - tx * ntY;
    const int row0 = tx * 64;
    const int col0 = ty * 128;
    if (row0 >= jb.M) return;

    const float* __restrict__ A = jb.A;
    const float* __restrict__ B = jb.B;
    const int M = jb.M;
    const int lda = jb.lda;
    const int N = jb.N;
    const int K = jb.K;

    __shared__ float As[2][16][68];
    __shared__ float Bs[2][16][128];
    __shared__ float fv_sh[8 * 128];

    const int t   = threadIdx.x;
    const int tc  = t & 31;
    const int tr  = t >> 5;

    const int arow = t >> 2;
    const int akq  = (t & 3) * 4;
    const int bs0k = t >> 5;
    const int bs0c = (t & 31) * 4;
    const int bs1k = bs0k + 8;
    const bool arow_ok = (row0 + arow < M);

    const bool do_alpha = (jb.fv != nullptr) && (ty == 0);
    if (do_alpha) {
        for (int i = t; i < jb.n_alpha * 128; i += 256) fv_sh[i] = jb.fv[i];
        __syncthreads();   // fv_sh ready before any alpha accumulation
    }
    float alp_acc[8];
    #pragma unroll
    for (int i = 0; i < 8; i++) alp_acc[i] = 0.f;

    unsigned long long acc2[4][4];
    #pragma unroll
    for (int i = 0; i < 4; i++)
        #pragma unroll
        for (int j = 0; j < 4; j++) acc2[i][j] = 0ull;

    // ---- prologue: load tile 0, stage into buffer 0 ----
    float4 av = make_float4(0.f, 0.f, 0.f, 0.f), bv0, bv1;
    if (arow_ok) {
        av = *(const float4*)(A + (size_t)(row0 + arow) * lda + akq);
        if (jb.A2) {
            float4 a2 = *(const float4*)(jb.A2 + (size_t)(row0 + arow) * lda + akq);
            av.x = fmaxf(av.x + a2.x, 0.f); av.y = fmaxf(av.y + a2.y, 0.f);
            av.z = fmaxf(av.z + a2.z, 0.f); av.w = fmaxf(av.w + a2.w, 0.f);
        }
    }
    bv0 = *(const float4*)(B + (size_t)bs0k * N + col0 + bs0c);
    bv1 = *(const float4*)(B + (size_t)bs1k * N + col0 + bs0c);
    if (do_alpha) {
        #pragma unroll
        for (int c = 0; c < 8; c++) {
            if (c < jb.n_alpha) {
                float4 fq = *(float4*)&fv_sh[c * 128 + akq];
                alp_acc[c] += av.x * fq.x + av.y * fq.y + av.z * fq.z + av.w * fq.w;
            }
        }
    }
    As[0][akq + 0][arow] = av.x;
    As[0][akq + 1][arow] = av.y;
    As[0][akq + 2][arow] = av.z;
    As[0][akq + 3][arow] = av.w;
    *(float4*)&Bs[0][bs0k][bs0c] = bv0;
    *(float4*)&Bs[0][bs1k][bs0c] = bv1;
    __syncthreads();

    const int nt = K >> 4;
    for (int it = 1; it < nt; it++) {
        const int k0 = it * 16;
        // prefetch tile it
        av = make_float4(0.f, 0.f, 0.f, 0.f);
        if (arow_ok) {
            av = *(const float4*)(A + (size_t)(row0 + arow) * lda + k0 + akq);
            if (jb.A2) {
                float4 a2 = *(const float4*)(jb.A2 + (size_t)(row0 + arow) * lda + k0 + akq);
                av.x = fmaxf(av.x + a2.x, 0.f); av.y = fmaxf(av.y + a2.y, 0.f);
                av.z = fmaxf(av.z + a2.z, 0.f); av.w = fmaxf(av.w + a2.w, 0.f);
            }
        }
        bv0 = *(const float4*)(B + (size_t)(k0 + bs0k) * N + col0 + bs0c);
        bv1 = *(const float4*)(B + (size_t)(k0 + bs1k) * N + col0 + bs0c);
        if (do_alpha) {
            #pragma unroll
            for (int c = 0; c < 8; c++) {
                if (c < jb.n_alpha) {
                    float4 fq = *(float4*)&fv_sh[c * 128 + k0 + akq];
                    alp_acc[c] += av.x * fq.x + av.y * fq.y + av.z * fq.z + av.w * fq.w;
                }
            }
        }
        // compute tile it-1 from buffer (it-1)&1
        {
            const int pb = (it - 1) & 1;
            #pragma unroll
            for (int kk = 0; kk < 16; kk++) {
                float4 bb = *(float4*)&Bs[pb][kk][tc * 4];
                ulonglong2 apA = *(ulonglong2*)&As[pb][kk][tr * 8];
                ulonglong2 apB = *(ulonglong2*)&As[pb][kk][tr * 8 + 4];
                unsigned long long ap0 = apA.x, ap1 = apA.y, ap2 = apB.x, ap3 = apB.y;
                unsigned long long bd0 = pk2(bb.x, bb.x);
                unsigned long long bd1 = pk2(bb.y, bb.y);
                unsigned long long bd2 = pk2(bb.z, bb.z);
                unsigned long long bd3 = pk2(bb.w, bb.w);
                fma2(acc2[0][0], ap0, bd0); fma2(acc2[0][1], ap0, bd1);
                fma2(acc2[0][2], ap0, bd2); fma2(acc2[0][3], ap0, bd3);
                fma2(acc2[1][0], ap1, bd0); fma2(acc2[1][1], ap1, bd1);
                fma2(acc2[1][2], ap1, bd2); fma2(acc2[1][3], ap1, bd3);
                fma2(acc2[2][0], ap2, bd0); fma2(acc2[2][1], ap2, bd1);
                fma2(acc2[2][2], ap2, bd2); fma2(acc2[2][3], ap2, bd3);
                fma2(acc2[3][0], ap3, bd0); fma2(acc2[3][1], ap3, bd1);
                fma2(acc2[3][2], ap3, bd2); fma2(acc2[3][3], ap3, bd3);
            }
        }
        // stage tile it into buffer it&1
        {
            const int cb = it & 1;
            As[cb][akq + 0][arow] = av.x;
            As[cb][akq + 1][arow] = av.y;
            As[cb][akq + 2][arow] = av.z;
            As[cb][akq + 3][arow] = av.w;
            *(float4*)&Bs[cb][bs0k][bs0c] = bv0;
            *(float4*)&Bs[cb][bs1k][bs0c] = bv1;
        }
        __syncthreads();
    }
    // tail compute: tile nt-1
    {
        const int pb = (nt - 1) & 1;
        #pragma unroll
        for (int kk = 0; kk < 16; kk++) {
            float4 bb = *(float4*)&Bs[pb][kk][tc * 4];
            ulonglong2 apA = *(ulonglong2*)&As[pb][kk][tr * 8];
            ulonglong2 apB = *(ulonglong2*)&As[pb][kk][tr * 8 + 4];
            unsigned long long ap0 = apA.x, ap1 = apA.y, ap2 = apB.x, ap3 = apB.y;
            unsigned long long bd0 = pk2(bb.x, bb.x);
            unsigned long long bd1 = pk2(bb.y, bb.y);
            unsigned long long bd2 = pk2(bb.z, bb.z);
            unsigned long long bd3 = pk2(bb.w, bb.w);
            fma2(acc2[0][0], ap0, bd0); fma2(acc2[0][1], ap0, bd1);
            fma2(acc2[0][2], ap0, bd2); fma2(acc2[0][3], ap0, bd3);
            fma2(acc2[1][0], ap1, bd0); fma2(acc2[1][1], ap1, bd1);
            fma2(acc2[1][2], ap1, bd2); fma2(acc2[1][3], ap1, bd3);
            fma2(acc2[2][0], ap2, bd0); fma2(acc2[2][1], ap2, bd1);
            fma2(acc2[2][2], ap2, bd2); fma2(acc2[2][3], ap2, bd3);
            fma2(acc2[3][0], ap3, bd0); fma2(acc2[3][1], ap3, bd1);
            fma2(acc2[3][2], ap3, bd2); fma2(acc2[3][3], ap3, bd3);
        }
    }

    // fused alpha epilogue: row owned by 4 consecutive threads
    if (do_alpha) {
        #pragma unroll
        for (int c = 0; c < 8; c++) {
            float v = alp_acc[c];
            v += __shfl_xor_sync(0xffffffffu, v, 1);
            v += __shfl_xor_sync(0xffffffffu, v, 2);
            alp_acc[c] = v;
        }
        if ((t & 3) == 0 && arow_ok) {
            for (int c = 0; c < jb.n_alpha; c++)
                jb.alp[(size_t)(row0 + arow) * jb.alp_ld + c] = alp_acc[c];
        }
    }

    float acc[8][4];
    #pragma unroll
    for (int i = 0; i < 4; i++)
        #pragma unroll
        for (int j = 0; j < 4; j++)
            upk2(acc2[i][j], acc[2 * i][j], acc[2 * i + 1][j]);

    float4 bv = make_float4(0.f, 0.f, 0.f, 0.f);
    if (jb.bias) bv = *(const float4*)(jb.bias + col0 + tc * 4);

    if (jb.g) {
        float4 gv  = *(const float4*)(jb.g  + tc * 4);
        float4 bev = *(const float4*)(jb.be + tc * 4);
        #pragma unroll
        for (int i = 0; i < 8; i++) {
            float4 o;
            o.x = acc[i][0] + bv.x; o.y = acc[i][1] + bv.y;
            o.z = acc[i][2] + bv.z; o.w = acc[i][3] + bv.w;
            float s  = warp_sum(o.x + o.y + o.z + o.w);
            float sq = warp_sum(o.x * o.x + o.y * o.y + o.z * o.z + o.w * o.w);
            float mu  = s * (1.f / 128.f);
            float var = sq * (1.f / 128.f) - mu * mu;
            float r = rsqrtf(var + 1e-5f);
            o.x = fmaxf((o.x - mu) * r * gv.x + bev.x, 0.f);
            o.y = fmaxf((o.y - mu) * r * gv.y + bev.y, 0.f);
            o.z = fmaxf((o.z - mu) * r * gv.z + bev.z, 0.f);
            o.w = fmaxf((o.w - mu) * r * gv.w + bev.w, 0.f);
            int row = row0 + tr * 8 + i;
            if (row < M)
                *(float4*)(jb.C + (size_t)row * jb.ldC + col0 + tc * 4) = o;
        }
    } else if (jb.qv) {
        float4 qv4 = *(const float4*)(jb.qv + tc * 4);
        #pragma unroll
        for (int i = 0; i < 8; i++) {
            int row = row0 + tr * 8 + i;
            float4 o;
            o.x = acc[i][0] + bv.x; o.y = acc[i][1] + bv.y;
            o.z = acc[i][2] + bv.z; o.w = acc[i][3] + bv.w;
            float dot = warp_sum(o.x * qv4.x + o.y * qv4.y + o.z * qv4.z + o.w * qv4.w);
            if (row < M) {
                *(float4*)(jb.C + (size_t)row * jb.ldC + tc * 4) = o;
                if (tc == 0) jb.sc[row] = dot;
            }
        }
    } else if (jb.Cb) {
        #pragma unroll
        for (int i = 0; i < 8; i++) {
            int row = row0 + tr * 8 + i;
            if (row < M) {
                float4 o;
                o.x = acc[i][0] + bv.x; o.y = acc[i][1] + bv.y;
                o.z = acc[i][2] + bv.z; o.w = acc[i][3] + bv.w;
                __nv_bfloat162 p0; p0.x = __float2bfloat16(o.x); p0.y = __float2bfloat16(o.y);
                __nv_bfloat162 p1; p1.x = __float2bfloat16(o.z); p1.y = __float2bfloat16(o.w);
                uint2 u = make_uint2(*(unsigned int*)&p0, *(unsigned int*)&p1);
                *(uint2*)(jb.Cb + (size_t)row * jb.ldC + col0 + tc * 4) = u;
            }
        }
    } else {
        #pragma unroll
        for (int i = 0; i < 8; i++) {
            int row = row0 + tr * 8 + i;
            if (row < M) {
                float4 o;
                o.x = acc[i][0] + bv.x; o.y = acc[i][1] + bv.y;
                o.z = acc[i][2] + bv.z; o.w = acc[i][3] + bv.w;
                *(float4*)(jb.C + (size_t)row * jb.ldC + col0 + tc * 4) = o;
            }
        }
    }
}

// ---------------- merged prep: fold_fv (0-23), fold_cvec (24-27), q (28), csr zero (29+) ----------------
#define ZERO_BLKS ((CNTCUR_N + 127) / 128)
__global__ void prep_kernel(const float* __restrict__ Ws, const float* __restrict__ Wd,
                            const float* __restrict__ as_, const float* __restrict__ ad_,
                            const float* __restrict__ gat_b,
                            const float* __restrict__ inter_W, const float* __restrict__ inter_b,
                            const float* __restrict__ query, const float* __restrict__ Wq,
                            const float* __restrict__ bq,
                            float* __restrict__ fvj, float* __restrict__ fvs,
                            float* __restrict__ cvj, float* __restrict__ cvs,
                            float* __restrict__ qout, int* __restrict__ cntcur)
{
    int bid = blockIdx.x;
    int k = threadIdx.x;
    if (bid >= 29) {
        int i = (bid - 29) * 128 + k;
        if (i < CNTCUR_N) cntcur[i] = 0;
        return;
    }
    if (bid < 24) {
        int l = bid / 12, v = bid % 12;
        int rel, h, col, useWd, isJob;
        if (v < 2)       { rel = 0; h = v;      col = v;     useWd = 0; isJob = 1; }
        else if (v < 4)  { rel = 1; h = v - 2;  col = v;     useWd = 1; isJob = 1; }
        else if (v < 6)  { rel = 1; h = v - 4;  col = v - 4; useWd = 0; isJob = 0; }
        else if (v < 8)  { rel = 2; h = v - 6;  col = v - 4; useWd = 0; isJob = 0; }
        else if (v < 10) { rel = 0; h = v - 8;  col = v - 4; useWd = 1; isJob = 0; }
        else             { rel = 2; h = v - 10; col = v - 4; useWd = 1; isJob = 0; }
        const float* W = (useWd ? Wd : Ws) + (size_t)(l * 3 + rel) * 32768 + h * 128;
        const float* a = (useWd ? ad_ : as_) + (size_t)((l * 3 + rel) * 2 + h) * 128;
        float acc = 0.f;
        #pragma unroll 8
        for (int c = 0; c < 128; c++) acc += W[(size_t)k * 256 + c] * a[c];
        float* out = isJob ? (fvj + l * 512) : (fvs + l * 1024);
        out[col * 128 + k] = acc;
    } else if (bid < 28) {
        int b2 = bid - 24;
        int l = b2 >> 1, t = b2 & 1;
        const float* W = inter_W + (size_t)(l * 2 + t) * 256 * 128;
        float acc = inter_b[(l * 2 + t) * 128 + k];
        if (t == 0) {
            const float* b = gat_b + (size_t)(l * 3 + 1) * 256;
            for (int c = 0; c < 256; c++) acc += b[c] * W[(size_t)c * 128 + k];
            cvj[l * 128 + k] = acc;
        } else {
            const float* b0 = gat_b + (size_t)(l * 3 + 0) * 256;
            const float* b2p = gat_b + (size_t)(l * 3 + 2) * 256;
            for (int c = 0; c < 256; c++) acc += (b0[c] + b2p[c]) * W[(size_t)c * 128 + k];
            cvs[l * 128 + k] = acc;
        }
    } else {
        float acc = bq[k];
        for (int c = 0; c < SBERT; c++) acc += query[c] * Wq[(size_t)c * 128 + k];
        qout[k] = acc;
    }
}

// ---------------- CSR build ----------------
__global__ void hist3_kernel(const int* __restrict__ js_d, const int* __restrict__ ss_d,
                             const int* __restrict__ sj_d,
                             int* __restrict__ cnt_js, int* __restrict__ cnt_ss,
                             int* __restrict__ cnt_sj)
{
    int e = blockIdx.x * blockDim.x + threadIdx.x;
    if (e >= E_ALL) return;
    if (e < E_JS)                  atomicAdd(&cnt_js[js_d[e]], 1);
    else if (e < E_JS + E_SS)      atomicAdd(&cnt_ss[ss_d[e - E_JS]], 1);
    else if (e < E_JS + E_SS + NS) atomicAdd(&cnt_ss[e - E_JS - E_SS], 1);
    else                           atomicAdd(&cnt_sj[sj_d[e - E_JS - E_SS_T]], 1);
}

__global__ void scan3_kernel(const int* __restrict__ cnt_js, int* __restrict__ off_js,
                             const int* __restrict__ cnt_ss, int* __restrict__ off_ss,
                             const int* __restrict__ cnt_sj, int* __restrict__ off_sj)
{
    const int* cnt; int* off; int n;
    if (blockIdx.x == 0)      { cnt = cnt_js; off = off_js; n = NS; }
    else if (blockIdx.x == 1) { cnt = cnt_ss; off = off_ss; n = NS; }
    else                      { cnt = cnt_sj; off = off_sj; n = NJ; }
    __shared__ int sh_carry;
    __shared__ int wsum[32];
    int lane = threadIdx.x & 31, wid = threadIdx.x >> 5;
    if (threadIdx.x == 0) sh_carry = 0;
    __syncthreads();
    for (int base = 0; base < n; base += 1024) {
        int i = base + threadIdx.x;
        int x = (i < n) ? cnt[i] : 0;
        int v = x;
        #pragma unroll
        for (int o = 1; o < 32; o <<= 1) {
            int tv = __shfl_up_sync(0xffffffffu, v, o);
            if (lane >= o) v += tv;
        }
        if (lane == 31) wsum[wid] = v;
        __syncthreads();
        if (wid == 0) {
            int s = wsum[lane];
            #pragma unroll
            for (int o = 1; o < 32; o <<= 1) {
                int tv = __shfl_up_sync(0xffffffffu, s, o);
                if (lane >= o) s += tv;
            }
            wsum[lane] = s;
        }
        __syncthreads();
        int pre = wid ? wsum[wid - 1] : 0;
        int incl = v + pre;
        int carry = sh_carry;
        if (i < n) off[i] = carry + incl - x;
        __syncthreads();
        if (threadIdx.x == 1023) sh_carry = carry + incl;
        __syncthreads();
    }
}

__global__ void fill3_kernel(const int* __restrict__ js_s, const int* __restrict__ js_d,
                             const int* __restrict__ ss_s, const int* __restrict__ ss_d,
                             const int* __restrict__ sj_s, const int* __restrict__ sj_d,
                             const int* __restrict__ off_js, int* __restrict__ cur_js,
                             int* __restrict__ csr_js,
                             const int* __restrict__ off_ss, int* __restrict__ cur_ss,
                             int* __restrict__ csr_ss,
                             const int* __restrict__ off_sj, int* __restrict__ cur_sj,
                             int* __restrict__ csr_sj)
{
    int e = blockIdx.x * blockDim.x + threadIdx.x;
    if (e >= E_ALL) return;
    int s, d;
    const int* off; int* cur; int* csr;
    if (e < E_JS) {
        s = js_s[e]; d = js_d[e]; off = off_js; cur = cur_js; csr = csr_js;
    } else if (e < E_JS + E_SS) {
        int i = e - E_JS; s = ss_s[i]; d = ss_d[i]; off = off_ss; cur = cur_ss; csr = csr_ss;
    } else if (e < E_JS + E_SS + NS) {
        s = d = e - E_JS - E_SS; off = off_ss; cur = cur_ss; csr = csr_ss;
    } else {
        int i = e - E_JS - E_SS_T; s = sj_s[i]; d = sj_d[i]; off = off_sj; cur = cur_sj; csr = csr_sj;
    }
    int pos = off[d] + atomicAdd(&cur[d], 1);
    csr[pos] = s;
}

// ---------------- softmax-aggregate: bf16 features ----------------
__device__ __forceinline__ void agg_one_bf(int o, int deg, const int* __restrict__ csrc,
                                           const __nv_bfloat16* __restrict__ hw,
                                           const float* __restrict__ alps, int ldh,
                                           float ad0, float ad1, int lane, float* out)
{
    if (deg <= 0) return;
    float acc[8];
    #pragma unroll
    for (int i = 0; i < 8; i++) acc[i] = 0.f;
    float den0 = 0.f, den1 = 0.f;
    const float2* ap = (const float2*)alps;

    int s  = csrc[o];
    int s1 = (deg > 1) ? csrc[o + 1] : 0;
    float2 av = ap[s * ldh];
    uint4 v = ((const uint4*)(hw + (size_t)s * 256))[lane];

    for (int k = 0; k < deg; k++) {
        int s2 = (k + 2 < deg) ? csrc[o + k + 2] : 0;
        float2 avn = ap[s1 * ldh];
        uint4 vn = ((const uint4*)(hw + (size_t)s1 * 256))[lane];

        float e0 = av.x + ad0; e0 = e0 > 0.f ? e0 : 0.2f * e0;
        float e1 = av.y + ad1; e1 = e1 > 0.f ? e1 : 0.2f * e1;
        float p0 = __expf(e0), p1 = __expf(e1);
        float pw = (lane < 16) ? p0 : p1;
        float2 f;
        f = bf2f(v.x); acc[0] = fmaf(pw, f.x, acc[0]); acc[1] = fmaf(pw, f.y, acc[1]);
        f = bf2f(v.y); acc[2] = fmaf(pw, f.x, acc[2]); acc[3] = fmaf(pw, f.y, acc[3]);
        f = bf2f(v.z); acc[4] = fmaf(pw, f.x, acc[4]); acc[5] = fmaf(pw, f.y, acc[5]);
        f = bf2f(v.w); acc[6] = fmaf(pw, f.x, acc[6]); acc[7] = fmaf(pw, f.y, acc[7]);
        den0 += p0; den1 += p1;

        s1 = s2; av = avn; v = vn;
    }
    float r = (lane < 16) ? 1.f / (den0 + 1e-16f) : 1.f / (den1 + 1e-16f);
    #pragma unroll
    for (int i = 0; i < 8; i++) {
        float tmp = acc[i] * r;
        out[i] += tmp + __shfl_xor_sync(0xffffffffu, tmp, 16);
    }
}

// ---------------- softmax-aggregate: fp32 features (layer 2) ----------------
__device__ __forceinline__ void agg_one_f32(int o, int deg, const int* __restrict__ csrc,
                                            const float* __restrict__ hwf,
                                            const float* __restrict__ alps, int ldh,
                                            float ad0, float ad1, int lane, float* out)
{
    if (deg <= 0) return;
    float acc[8];
    #pragma unroll
    for (int i = 0; i < 8; i++) acc[i] = 0.f;
    float den0 = 0.f, den1 = 0.f;
    const float2* ap = (const float2*)alps;
    const int hb = ((lane < 16) ? 0 : 128) + (lane & 15) * 8;

    int s  = csrc[o];
    int s1 = (deg > 1) ? csrc[o + 1] : 0;
    float2 av = ap[s * ldh];
    float4 va = *(const float4*)(hwf + (size_t)s * 256 + hb);
    float4 vb = *(const float4*)(hwf + (size_t)s * 256 + hb + 4);

    for (int k = 0; k < deg; k++) {
        int s2 = (k + 2 < deg) ? csrc[o + k + 2] : 0;
        float2 avn = ap[s1 * ldh];
        float4 van = *(const float4*)(hwf + (size_t)s1 * 256 + hb);
        float4 vbn = *(const float4*)(hwf + (size_t)s1 * 256 + hb + 4);

        float e0 = av.x + ad0; e0 = e0 > 0.f ? e0 : 0.2f * e0;
        float e1 = av.y + ad1; e1 = e1 > 0.f ? e1 : 0.2f * e1;
        float p0 = __expf(e0), p1 = __expf(e1);
        float pw = (lane < 16) ? p0 : p1;
        acc[0] = fmaf(pw, va.x, acc[0]); acc[1] = fmaf(pw, va.y, acc[1]);
        acc[2] = fmaf(pw, va.z, acc[2]); acc[3] = fmaf(pw, va.w, acc[3]);
        acc[4] = fmaf(pw, vb.x, acc[4]); acc[5] = fmaf(pw, vb.y, acc[5]);
        acc[6] = fmaf(pw, vb.z, acc[6]); acc[7] = fmaf(pw, vb.w, acc[7]);
        den0 += p0; den1 += p1;

        s1 = s2; av = avn; va = van; vb = vbn;
    }
    float r = (lane < 16) ? 1.f / (den0 + 1e-16f) : 1.f / (den1 + 1e-16f);
    #pragma unroll
    for (int i = 0; i < 8; i++) {
        float tmp = acc[i] * r;
        out[i] += tmp + __shfl_xor_sync(0xffffffffu, tmp, 16);
    }
}

// ---------------- fused aggregation + folded inter linear ----------------
__global__ void gat_kernel(const int* __restrict__ off_js, const int* __restrict__ cnt_js,
                           const int* __restrict__ csr_js,
                           const int* __restrict__ off_ss, const int* __restrict__ cnt_ss,
                           const int* __restrict__ csr_ss,
                           const int* __restrict__ off_sj, const int* __restrict__ cnt_sj,
                           const int* __restrict__ csr_sj,
                           const __nv_bfloat16* __restrict__ hw0,
                           const __nv_bfloat16* __restrict__ hw1,
                           const __nv_bfloat16* __restrict__ hw2,
                           const float* __restrict__ hw1f,
                           const float* __restrict__ alpj, const float* __restrict__ alp_s,
                           const float* __restrict__ cvj, const float* __restrict__ cvs,
                           const float* __restrict__ fvj2,
                           float* __restrict__ xj, float* __restrict__ xs,
                           float* __restrict__ xs2,
                           float* __restrict__ alpj_out, int layer)
{
    int w    = (blockIdx.x * blockDim.x + threadIdx.x) >> 5;
    int lane = threadIdx.x & 31;
    int lc   = (lane & 15) * 8;
    float out[8];
    if (layer == 0) {
        if (w < NS) {
            int d = w;
            #pragma unroll
            for (int i = 0; i < 8; i++) out[i] = cvs[lc + i];
            agg_one_bf(off_js[d], cnt_js[d], csr_js, hw0, alpj, 2,
                       alp_s[d * 8 + 4], alp_s[d * 8 + 5], lane, out);
            if (lane < 16) {
                float4* op = (float4*)(xs + (size_t)d * 128 + lc);
                op[0] = make_float4(out[0], out[1], out[2], out[3]);
                op[1] = make_float4(out[4], out[5], out[6], out[7]);
            }
        } else if (w < 2 * NS) {
            int d = w - NS;
            #pragma unroll
            for (int i = 0; i < 8; i++) out[i] = 0.f;
            agg_one_bf(off_ss[d], cnt_ss[d], csr_ss, hw2, alp_s + 2, 4,
                       alp_s[d * 8 + 6], alp_s[d * 8 + 7], lane, out);
            if (lane < 16) {
                float4* op = (float4*)(xs2 + (size_t)d * 128 + lc);
                op[0] = make_float4(out[0], out[1], out[2], out[3]);
                op[1] = make_float4(out[4], out[5], out[6], out[7]);
            }
        } else if (w < 2 * NS + NJ) {
            int d = w - 2 * NS;
            #pragma unroll
            for (int i = 0; i < 8; i++) out[i] = cvj[lc + i];
            agg_one_bf(off_sj[d], cnt_sj[d], csr_sj, hw1, alp_s, 4,
                       alpj[d * 4 + 2], alpj[d * 4 + 3], lane, out);
            #pragma unroll
            for (int i = 0; i < 8; i++) out[i] = fmaxf(out[i], 0.f);
            float a2p = 0.f, a3p = 0.f;
            if (lane < 16) {
                float4* op = (float4*)(xj + (size_t)d * 128 + lc);
                op[0] = make_float4(out[0], out[1], out[2], out[3]);
                op[1] = make_float4(out[4], out[5], out[6], out[7]);
                #pragma unroll
                for (int i = 0; i < 8; i++) {
                    a2p += out[i] * fvj2[2 * 128 + lc + i];
                    a3p += out[i] * fvj2[3 * 128 + lc + i];
                }
            }
            float a2 = warp_sum(a2p);
            float a3 = warp_sum(a3p);
            if (lane == 0) { alpj_out[d * 4 + 2] = a2; alpj_out[d * 4 + 3] = a3; }
        }
    } else {
        if (w < NJ) {
            int d = w;
            #pragma unroll
            for (int i = 0; i < 8; i++) out[i] = cvj[lc + i];
            agg_one_f32(off_sj[d], cnt_sj[d], csr_sj, hw1f, alp_s, 4,
                        alpj[d * 4 + 2], alpj[d * 4 + 3], lane, out);
            if (lane < 16) {
                float4* op = (float4*)(xj + (size_t)d * 128 + lc);
                op[0] = make_float4(fmaxf(out[0], 0.f), fmaxf(out[1], 0.f),
                                    fmaxf(out[2], 0.f), fmaxf(out[3], 0.f));
                op[1] = make_float4(fmaxf(out[4], 0.f), fmaxf(out[5], 0.f),
                                    fmaxf(out[6], 0.f), fmaxf(out[7], 0.f));
            }
        }
    }
}

// ---------------- host ----------------
static inline int tiles_of(int M, int N) { return ((M + 63) / 64) * (N >> 7); }

extern "C" void kernel_launch(void* const* d_in, const int* in_sizes, int n_in,
                              void* d_out, int out_size)
{
    const float* x_job    = (const float*)d_in[0];
    const float* x_skill  = (const float*)d_in[1];
    const int*   ei_js_s  = (const int*)d_in[2];
    const int*   ei_js_d  = (const int*)d_in[3];
    const int*   ei_sj_s  = (const int*)d_in[4];
    const int*   ei_sj_d  = (const int*)d_in[5];
    const int*   ei_ss_s  = (const int*)d_in[6];
    const int*   ei_ss_d  = (const int*)d_in[7];
    const float* query    = (const float*)d_in[8];
    const float* W0_job   = (const float*)d_in[9];
    const float* b0_job   = (const float*)d_in[10];
    const float* g0_job   = (const float*)d_in[11];
    const float* be0_job  = (const float*)d_in[12];
    const float* W0_skill = (const float*)d_in[13];
    const float* b0_skill = (const float*)d_in[14];
    const float* g0_skill = (const float*)d_in[15];
    const float* be0_skill= (const float*)d_in[16];
    const float* gat_Ws   = (const float*)d_in[17];
    const float* gat_Wd   = (const float*)d_in[18];
    const float* gat_as   = (const float*)d_in[19];
    const float* gat_ad   = (const float*)d_in[20];
    const float* gat_b    = (const float*)d_in[21];
    const float* inter_W  = (const float*)d_in[22];
    const float* inter_b  = (const float*)d_in[23];
    const float* Wjf      = (const float*)d_in[24];
    const float* bjf      = (const float*)d_in[25];
    const float* Wq       = (const float*)d_in[26];
    const float* bq       = (const float*)d_in[27];

    float* out     = (float*)d_out;
    float* scores  = out;
    float* job_emb = out + NJ;
    float* qout    = out + NJ + (size_t)NJ * 128;

    void* p;
    cudaGetSymbolAddress(&p, g_xj);    float* xj    = (float*)p;
    cudaGetSymbolAddress(&p, g_xs);    float* xs    = (float*)p;
    cudaGetSymbolAddress(&p, g_xs2);   float* xs2   = (float*)p;
    cudaGetSymbolAddress(&p, g_hw0);   __nv_bfloat16* hw0 = (__nv_bfloat16*)p;
    cudaGetSymbolAddress(&p, g_hw1);   __nv_bfloat16* hw1 = (__nv_bfloat16*)p;
    cudaGetSymbolAddress(&p, g_hw2);   __nv_bfloat16* hw2 = (__nv_bfloat16*)p;
    cudaGetSymbolAddress(&p, g_hw1f);  float* hw1f  = (float*)p;
    cudaGetSymbolAddress(&p, g_mw);    float* mw    = (float*)p;
    cudaGetSymbolAddress(&p, g_fvj);   float* fvj   = (float*)p;
    cudaGetSymbolAddress(&p, g_fvs);   float* fvs   = (float*)p;
    cudaGetSymbolAddress(&p, g_cvj);   float* cvj   = (float*)p;
    cudaGetSymbolAddress(&p, g_cvs);   float* cvs   = (float*)p;
    cudaGetSymbolAddress(&p, g_alpj);  float* alpj  = (float*)p;
    cudaGetSymbolAddress(&p, g_alp_s); float* alp_s = (float*)p;
    cudaGetSymbolAddress(&p, g_cntcur); int* cntcur = (int*)p;
    int* cnt_js = cntcur;
    int* cur_js = cntcur + NS;
    int* cnt_ss = cntcur + 2 * NS;
    int* cur_ss = cntcur + 3 * NS;
    int* cnt_sj = cntcur + 4 * NS;
    int* cur_sj = cntcur + 4 * NS + NJ;
    cudaGetSymbolAddress(&p, g_off_js); int* off_js = (int*)p;
    cudaGetSymbolAddress(&p, g_off_ss); int* off_ss = (int*)p;
    cudaGetSymbolAddress(&p, g_off_sj); int* off_sj = (int*)p;
    cudaGetSymbolAddress(&p, g_csr_js); int* csr_js = (int*)p;
    cudaGetSymbolAddress(&p, g_csr_ss); int* csr_ss = (int*)p;
    cudaGetSymbolAddress(&p, g_csr_sj); int* csr_sj = (int*)p;

    GJobs J;

    // ---- prep (fv, cvec, q, csr-zero) ----
    prep_kernel<<<29 + ZERO_BLKS, 128>>>(gat_Ws, gat_Wd, gat_as, gat_ad, gat_b, inter_W, inter_b,
                                         query, Wq, bq, fvj, fvs, cvj, cvs, qout, cntcur);

    // ---- CSR build ----
    hist3_kernel<<<(E_ALL + 255) / 256, 256>>>(ei_js_d, ei_ss_d, ei_sj_d, cnt_js, cnt_ss, cnt_sj);
    scan3_kernel<<<3, 1024>>>(cnt_js, off_js, cnt_ss, off_ss, cnt_sj, off_sj);
    fill3_kernel<<<(E_ALL + 255) / 256, 256>>>(ei_js_s, ei_js_d, ei_ss_s, ei_ss_d, ei_sj_s, ei_sj_d,
                                               off_js, cur_js, csr_js,
                                               off_ss, cur_ss, csr_ss,
                                               off_sj, cur_sj, csr_sj);

    // ---- launch A: 8 MW folds + 2 initial projections (all N=128) ----
    {
        int tt = 0;
        for (int z = 0; z < 10; z++) J.j[z] = GJob{};
        for (int r = 0; r < 3; r++) {
            int t = (r == 1) ? 0 : 1;
            for (int h = 0; h < 2; h++) {
                GJob& jj = J.j[r * 2 + h];
                jj.A = gat_Ws + (size_t)r * 32768 + h * 128;
                jj.B = inter_W + (size_t)t * 32768 + (size_t)h * 16384;
                jj.C = mw + (size_t)r * 32768 + h * 128;
                jj.M = 128; jj.lda = 256; jj.ldC = 256; jj.N = 128; jj.K = 128;
                jj.tstart = tt; tt += tiles_of(128, 128);
            }
        }
        for (int h = 0; h < 2; h++) {
            GJob& jj = J.j[6 + h];
            // overwrite slots 6,7 were layer0 r=2? No: r loop used slots 0..5; use 6,7 for layer-1 rel1
        }
        // slots 6,7: layer-1 rel-1 folds
        for (int h = 0; h < 2; h++) {
            GJob& jj = J.j[6 + h];
            jj.A = gat_Ws + (size_t)(3 + 1) * 32768 + h * 128;
            jj.B = inter_W + (size_t)(2 + 0) * 32768 + (size_t)h * 16384;
            jj.C = mw + (size_t)(3 + 1) * 32768 + h * 128;
            jj.M = 128; jj.lda = 256; jj.ldC = 256; jj.N = 128; jj.K = 128;
            jj.tstart = tt; tt += tiles_of(128, 128);
        }
        // wait — slots 4,5 were r=2 folds; re-lay slots: r=0→0,1; r=1→2,3; r=2→4,5; layer1 rel1→6,7
        // (the loop above already placed r*2+h correctly for r<3)
        GJob& j8 = J.j[8];
        j8.A = x_job; j8.B = W0_job; j8.bias = b0_job; j8.g = g0_job; j8.be = be0_job;
        j8.C = xj; j8.M = NJ; j8.lda = SBERT; j8.ldC = 128; j8.N = 128; j8.K = SBERT;
        j8.tstart = tt; tt += tiles_of(NJ, 128);
        GJob& j9 = J.j[9];
        j9.A = x_skill; j9.B = W0_skill; j9.bias = b0_skill; j9.g = g0_skill; j9.be = be0_skill;
        j9.C = xs; j9.M = NS; j9.lda = SBERT; j9.ldC = 128; j9.N = 128; j9.K = SBERT;
        j9.tstart = tt; tt += tiles_of(NS, 128);
        gemm_kernel<<<tt, 256>>>(J);
    }

    // ---- launch B: layer-1 hw GEMMs (bf16 out) with fused alpha ----
    {
        int tt = 0;
        for (int z = 0; z < 10; z++) J.j[z] = GJob{};
        J.j[0].A = xj; J.j[0].B = mw + 0 * 32768; J.j[0].Cb = hw0;
        J.j[0].M = NJ; J.j[0].lda = 128; J.j[0].ldC = 256; J.j[0].N = 256; J.j[0].K = 128;
        J.j[0].fv = fvj; J.j[0].alp = alpj; J.j[0].n_alpha = 4; J.j[0].alp_ld = 4;
        J.j[0].tstart = tt; tt += tiles_of(NJ, 256);
        J.j[1].A = xs; J.j[1].B = mw + 1 * 32768; J.j[1].Cb = hw1;
        J.j[1].M = NS; J.j[1].lda = 128; J.j[1].ldC = 256; J.j[1].N = 256; J.j[1].K = 128;
        J.j[1].fv = fvs; J.j[1].alp = alp_s; J.j[1].n_alpha = 8; J.j[1].alp_ld = 8;
        J.j[1].tstart = tt; tt += tiles_of(NS, 256);
        J.j[2].A = xs; J.j[2].B = mw + 2 * 32768; J.j[2].Cb = hw2;
        J.j[2].M = NS; J.j[2].lda = 128; J.j[2].ldC = 256; J.j[2].N = 256; J.j[2].K = 128;
        J.j[2].tstart = tt; tt += tiles_of(NS, 256);
        gemm_kernel<<<tt, 256>>>(J);
    }

    gat_kernel<<<((2 * NS + NJ) * 32 + 255) / 256, 256>>>(
        off_js, cnt_js, csr_js, off_ss, cnt_ss, csr_ss, off_sj, cnt_sj, csr_sj,
        hw0, hw1, hw2, hw1f, alpj, alp_s,
        cvj, cvs, fvj + 512, xj, xs, xs2, alpj, 0);

    // ---- launch C: layer-2 GEMM (fp32 out) with fused alps1 ----
    {
        int tt = 0;
        for (int z = 0; z < 10; z++) J.j[z] = GJob{};
        J.j[0].A = xs; J.j[0].A2 = xs2; J.j[0].B = mw + (size_t)(3 + 1) * 32768; J.j[0].C = hw1f;
        J.j[0].M = NS; J.j[0].lda = 128; J.j[0].ldC = 256; J.j[0].N = 256; J.j[0].K = 128;
        J.j[0].fv = fvs + 1024; J.j[0].alp = alp_s; J.j[0].n_alpha = 2; J.j[0].alp_ld = 8;
        J.j[0].tstart = tt; tt += tiles_of(NS, 256);
        gemm_kernel<<<tt, 256>>>(J);
    }

    gat_kernel<<<(NJ * 32 + 255) / 256, 256>>>(
        off_js, cnt_js, csr_js, off_ss, cnt_ss, csr_ss, off_sj, cnt_sj, csr_sj,
        hw0, hw1, hw2, hw1f, alpj, alp_s,
        cvj + 128, cvs + 128, fvj + 512, xj, xs, xs2, alpj, 1);

    // ---- launch D: final projection + fused scores ----
    {
        int tt = 0;
        for (int z = 0; z < 10; z++) J.j[z] = GJob{};
        J.j[0].A = xj; J.j[0].B = Wjf; J.j[0].bias = bjf; J.j[0].qv = qout;
        J.j[0].C = job_emb; J.j[0].sc = scores;
        J.j[0].M = NJ; J.j[0].lda = 128; J.j[0].ldC = 128; J.j[0].N = 128; J.j[0].K = 128;
        J.j[0].tstart = tt; tt += tiles_of(NJ, 128);
        gemm_kernel<<<tt, 256>>>(J);
    }
}